// round 1
// baseline (speedup 1.0000x reference)
#include <cuda_runtime.h>

// Problem constants: mat_1 [8192,128] f32, mat_2 [8192,128] f32, out [8192,8192] f32
#define DIMK 128
#define MAXROWS 8192

#define BM 128
#define BN 128
#define BK 32
#define TM 8
#define TN 8
#define PAD 4
#define NTHREADS 256

// Scratch for row norms (allocation-free rule: __device__ globals)
__device__ float g_sq1[MAXROWS];
__device__ float g_sq2[MAXROWS];

// One warp per row: 128 floats = 32 lanes x float4, butterfly reduce.
__global__ void row_norms_kernel(const float* __restrict__ m,
                                 float* __restrict__ out, int nrows) {
    int warp = (blockIdx.x * blockDim.x + threadIdx.x) >> 5;
    int lane = threadIdx.x & 31;
    if (warp >= nrows) return;
    float4 v = reinterpret_cast<const float4*>(m + (size_t)warp * DIMK)[lane];
    float s = v.x * v.x + v.y * v.y + v.z * v.z + v.w * v.w;
#pragma unroll
    for (int o = 16; o > 0; o >>= 1) s += __shfl_xor_sync(0xffffffffu, s, o);
    if (lane == 0) out[warp] = s;
}

// 128x128 output tile per CTA, 8x8 per thread, K consumed in 32-wide chunks.
// Tiles stored K-major-transposed in smem (As[k][m], Bs[k][n]) so the inner
// loop reads are conflict-free broadcasts/stride-1.
__global__ __launch_bounds__(NTHREADS, 2)
void euclid_gemm_kernel(const float* __restrict__ A,
                        const float* __restrict__ B,
                        const float* __restrict__ sq1,
                        const float* __restrict__ sq2,
                        float* __restrict__ C, int n2) {
    __shared__ float As[BK][BM + PAD];
    __shared__ float Bs[BK][BN + PAD];

    const int tid = threadIdx.x;
    const int tx = tid & 15;   // n direction (16 threads)
    const int ty = tid >> 4;   // m direction (16 threads)
    const int m0 = blockIdx.y * BM;
    const int n0 = blockIdx.x * BN;

    float acc[TM][TN];
#pragma unroll
    for (int i = 0; i < TM; i++)
#pragma unroll
        for (int j = 0; j < TN; j++) acc[i][j] = 0.0f;

#pragma unroll
    for (int k0 = 0; k0 < DIMK; k0 += BK) {
        // Load A tile: 128 rows x 32 k -> As[k][m]. 1024 float4s over 256 thr.
#pragma unroll
        for (int l = 0; l < 4; l++) {
            int idx = tid + NTHREADS * l;
            int row = idx >> 3;      // 0..127
            int kq = idx & 7;        // float4 index within 32-k chunk
            float4 v = *reinterpret_cast<const float4*>(
                A + (size_t)(m0 + row) * DIMK + k0 + kq * 4);
            As[kq * 4 + 0][row] = v.x;
            As[kq * 4 + 1][row] = v.y;
            As[kq * 4 + 2][row] = v.z;
            As[kq * 4 + 3][row] = v.w;
        }
#pragma unroll
        for (int l = 0; l < 4; l++) {
            int idx = tid + NTHREADS * l;
            int row = idx >> 3;
            int kq = idx & 7;
            float4 v = *reinterpret_cast<const float4*>(
                B + (size_t)(n0 + row) * DIMK + k0 + kq * 4);
            Bs[kq * 4 + 0][row] = v.x;
            Bs[kq * 4 + 1][row] = v.y;
            Bs[kq * 4 + 2][row] = v.z;
            Bs[kq * 4 + 3][row] = v.w;
        }
        __syncthreads();

#pragma unroll
        for (int k = 0; k < BK; k++) {
            float ra[TM], rb[TN];
#pragma unroll
            for (int i = 0; i < TM; i++) ra[i] = As[k][ty * TM + i];
#pragma unroll
            for (int j = 0; j < TN; j++) rb[j] = Bs[k][tx * TN + j];
#pragma unroll
            for (int i = 0; i < TM; i++)
#pragma unroll
                for (int j = 0; j < TN; j++)
                    acc[i][j] = fmaf(ra[i], rb[j], acc[i][j]);
        }
        __syncthreads();
    }

    // Epilogue: D = sq1[m] + sq2[n] - 2*dot, written as float4s.
    float s2[TN];
#pragma unroll
    for (int j = 0; j < TN; j++) s2[j] = sq2[n0 + tx * TN + j];

#pragma unroll
    for (int i = 0; i < TM; i++) {
        int m = m0 + ty * TM + i;
        float s1 = sq1[m];
        float* crow = C + (size_t)m * n2 + n0 + tx * TN;
#pragma unroll
        for (int j = 0; j < TN; j += 4) {
            float4 o;
            o.x = s1 + s2[j + 0] - 2.0f * acc[i][j + 0];
            o.y = s1 + s2[j + 1] - 2.0f * acc[i][j + 1];
            o.z = s1 + s2[j + 2] - 2.0f * acc[i][j + 2];
            o.w = s1 + s2[j + 3] - 2.0f * acc[i][j + 3];
            *reinterpret_cast<float4*>(crow + j) = o;
        }
    }
}

extern "C" void kernel_launch(void* const* d_in, const int* in_sizes, int n_in,
                              void* d_out, int out_size) {
    const float* A = (const float*)d_in[0];
    const float* B = (const float*)d_in[1];
    float* C = (float*)d_out;

    int n1 = in_sizes[0] / DIMK;  // 8192
    int n2 = in_sizes[1] / DIMK;  // 8192

    float* sq1;
    float* sq2;
    cudaGetSymbolAddress((void**)&sq1, g_sq1);
    cudaGetSymbolAddress((void**)&sq2, g_sq2);

    // Row norms: 8 warps per 256-thread block -> one warp per row.
    int nblk1 = (n1 + 7) / 8;
    int nblk2 = (n2 + 7) / 8;
    row_norms_kernel<<<nblk1, 256>>>(A, sq1, n1);
    row_norms_kernel<<<nblk2, 256>>>(B, sq2, n2);

    dim3 grid(n2 / BN, n1 / BM);
    euclid_gemm_kernel<<<grid, NTHREADS>>>(A, B, sq1, sq2, C, n2);
}

// round 4
// speedup vs baseline: 3.1225x; 3.1225x over previous
#include <cuda_runtime.h>
#include <cstdint>

// EuclideanDistance: mat_1 [8192,128] f32, mat_2 [8192,128] f32 -> out [8192,8192] f32
// D[i,j] = ||a_i||^2 + ||b_j||^2 - 2 * (A B^T)[i,j]
// GEMM core: mma.sync.m16n8k8 TF32 (baseline PTX path; tcgen05 unavailable:
// harness compiles for plain sm_103 target without the 'a' feature set).

#define NR 8192
#define DK 128
#define NTHREADS 256

__device__ float g_sq1[NR];
__device__ float g_sq2[NR];
__device__ float g_A32[NR * DK];   // tf32-rounded copies (cvt.rna)
__device__ float g_B32[NR * DK];

// ---------------- GEMM smem layout ----------------
// f32 tiles, 128 rows x 132 floats (528B rows = 33 x 16B, odd -> conflict-free ldmatrix)
#define ROWB 528
#define SMA 0
#define SMB0 67584
#define SMB1 135168
#define SM_TOTAL 202752

__device__ __forceinline__ uint32_t smem_u32(const void* p) {
    uint32_t a;
    asm("{ .reg .u64 t; cvta.to.shared.u64 t, %1; cvt.u32.u64 %0, t; }" : "=r"(a) : "l"(p));
    return a;
}

__device__ __forceinline__ void cpa16(uint32_t saddr, const void* gaddr) {
    asm volatile("cp.async.cg.shared.global [%0], [%1], 16;" :: "r"(saddr), "l"(gaddr));
}
__device__ __forceinline__ void cpa_commit() {
    asm volatile("cp.async.commit_group;" ::: "memory");
}

// ldmatrix on f32 data: each 8x8 b16 matrix = 8 rows x 4 floats; thread l gets
// the single f32 at (row=l/4, col=l%4) -> exactly the tf32 m16n8k8 fragment.
#define LDSM_X4(r0, r1, r2, r3, addr) \
    asm volatile("ldmatrix.sync.aligned.m8n8.x4.shared.b16 {%0,%1,%2,%3}, [%4];" \
                 : "=r"(r0), "=r"(r1), "=r"(r2), "=r"(r3) : "r"(addr))
#define LDSM_X2(r0, r1, addr) \
    asm volatile("ldmatrix.sync.aligned.m8n8.x2.shared.b16 {%0,%1}, [%2];" \
                 : "=r"(r0), "=r"(r1) : "r"(addr))

#define MMA_TF32(c, a0, a1, a2, a3, b0, b1) \
    asm volatile("mma.sync.aligned.m16n8k8.row.col.f32.tf32.tf32.f32 " \
                 "{%0,%1,%2,%3}, {%4,%5,%6,%7}, {%8,%9}, {%0,%1,%2,%3};" \
                 : "+f"((c)[0]), "+f"((c)[1]), "+f"((c)[2]), "+f"((c)[3]) \
                 : "r"(a0), "r"(a1), "r"(a2), "r"(a3), "r"(b0), "r"(b1))

// Load a 128x128 f32 tile (row-major, 512B rows) into padded smem rows via cp.async.
__device__ __forceinline__ void load_tile(const float* __restrict__ src,
                                          uint32_t smem_tile, int tid) {
#pragma unroll
    for (int l = 0; l < 16; l++) {
        int idx = tid + NTHREADS * l;   // 0..4095 16B segments
        int row = idx >> 5;             // 0..127
        int seg = idx & 31;             // 0..31
        cpa16(smem_tile + row * ROWB + seg * 16, src + (size_t)row * DK + seg * 4);
    }
}

__global__ void __launch_bounds__(NTHREADS, 1)
euclid_mma_kernel(const float* __restrict__ A32, const float* __restrict__ B32,
                  const float* __restrict__ sq1g, const float* __restrict__ sq2g,
                  float* __restrict__ C) {
    extern __shared__ char smem[];
    const uint32_t sb = smem_u32(smem);
    const int tid = threadIdx.x;
    const int lane = tid & 31;
    const int wid = tid >> 5;
    const int wm = wid & 1;       // warp m: 0..1 (64 rows each)
    const int wn = wid >> 1;      // warp n: 0..3 (32 cols each)
    const int mbase = blockIdx.y * 128;
    const int ntile0 = blockIdx.x * 4;

    // Prologue: A strip + B tile 0 (one commit group)
    load_tile(A32 + (size_t)mbase * DK, sb + SMA, tid);
    load_tile(B32 + (size_t)ntile0 * 128 * DK, sb + SMB0, tid);
    cpa_commit();

    // sq1 for this thread's output rows (fixed for whole CTA)
    float s1r[4][2];
#pragma unroll
    for (int mf = 0; mf < 4; mf++) {
        int m = mbase + wm * 64 + mf * 16 + (lane >> 2);
        s1r[mf][0] = sq1g[m];
        s1r[mf][1] = sq1g[m + 8];
    }

    // ldmatrix base addresses
    uint32_t aBase[4];
#pragma unroll
    for (int mf = 0; mf < 4; mf++) {
        int r = wm * 64 + mf * 16 + (lane & 15);
        aBase[mf] = sb + SMA + r * ROWB + ((lane >> 4) << 4);
    }
    uint32_t bOff[4];
#pragma unroll
    for (int nf = 0; nf < 4; nf++) {
        int r = wn * 32 + nf * 8 + (lane & 7);
        bOff[nf] = r * ROWB + (((lane >> 3) & 1) << 4);
    }

#pragma unroll 1
    for (int t = 0; t < 4; t++) {
        const uint32_t bufCur = (t & 1) ? SMB1 : SMB0;
        const uint32_t bufNext = (t & 1) ? SMB0 : SMB1;

        // Prefetch next B tile (its buffer was last read in iter t-1; the
        // end-of-iter __syncthreads guarantees those reads completed).
        if (t < 3) {
            load_tile(B32 + (size_t)(ntile0 + t + 1) * 128 * DK, sb + bufNext, tid);
            cpa_commit();
            asm volatile("cp.async.wait_group 1;" ::: "memory");
        } else {
            asm volatile("cp.async.wait_group 0;" ::: "memory");
        }
        __syncthreads();

        // sq2 for this tile's output cols
        const int nb = (ntile0 + t) * 128 + wn * 32;
        float s2r[4][2];
#pragma unroll
        for (int nf = 0; nf < 4; nf++) {
            int n = nb + nf * 8 + 2 * (lane & 3);
            s2r[nf][0] = sq2g[n];
            s2r[nf][1] = sq2g[n + 1];
        }

        float acc[4][4][4];
#pragma unroll
        for (int mf = 0; mf < 4; mf++)
#pragma unroll
            for (int nf = 0; nf < 4; nf++)
#pragma unroll
                for (int q = 0; q < 4; q++) acc[mf][nf][q] = 0.0f;

        // K = 128 in 16 k-steps of 8
#pragma unroll
        for (int ks = 0; ks < 16; ks++) {
            uint32_t a[4][4], b[4][2];
#pragma unroll
            for (int mf = 0; mf < 4; mf++)
                LDSM_X4(a[mf][0], a[mf][1], a[mf][2], a[mf][3], aBase[mf] + ks * 32);
#pragma unroll
            for (int nf = 0; nf < 4; nf++)
                LDSM_X2(b[nf][0], b[nf][1], sb + bufCur + bOff[nf] + ks * 32);
#pragma unroll
            for (int mf = 0; mf < 4; mf++)
#pragma unroll
                for (int nf = 0; nf < 4; nf++)
                    MMA_TF32(acc[mf][nf], a[mf][0], a[mf][1], a[mf][2], a[mf][3],
                             b[nf][0], b[nf][1]);
        }

        // Epilogue: D = sq1 + sq2 - 2*dot, float2 stores (32B-sector aligned)
#pragma unroll
        for (int mf = 0; mf < 4; mf++) {
            size_t m = (size_t)(mbase + wm * 64 + mf * 16 + (lane >> 2));
#pragma unroll
            for (int nf = 0; nf < 4; nf++) {
                int n = nb + nf * 8 + 2 * (lane & 3);
                float2 o0, o1;
                o0.x = fmaf(acc[mf][nf][0], -2.0f, s1r[mf][0] + s2r[nf][0]);
                o0.y = fmaf(acc[mf][nf][1], -2.0f, s1r[mf][0] + s2r[nf][1]);
                o1.x = fmaf(acc[mf][nf][2], -2.0f, s1r[mf][1] + s2r[nf][0]);
                o1.y = fmaf(acc[mf][nf][3], -2.0f, s1r[mf][1] + s2r[nf][1]);
                *reinterpret_cast<float2*>(C + m * NR + n) = o0;
                *reinterpret_cast<float2*>(C + (m + 8) * NR + n) = o1;
            }
        }
        __syncthreads();  // all reads of bufCur done before next prefetch overwrites it
    }
}

// Prep: row norms (exact f32, matching reference) + tf32-rounded copies (cvt.rna).
__global__ void prep_kernel(const float* __restrict__ A, const float* __restrict__ B,
                            float* __restrict__ A32, float* __restrict__ B32,
                            float* __restrict__ sq1, float* __restrict__ sq2) {
    int w = (blockIdx.x * blockDim.x + threadIdx.x) >> 5;
    int lane = threadIdx.x & 31;
    const float* src;
    float* dst;
    float* nrm;
    int row;
    if (w < NR) {
        src = A; dst = A32; nrm = sq1; row = w;
    } else {
        src = B; dst = B32; nrm = sq2; row = w - NR;
    }
    float4 v = reinterpret_cast<const float4*>(src + (size_t)row * DK)[lane];
    float s = v.x * v.x + v.y * v.y + v.z * v.z + v.w * v.w;
#pragma unroll
    for (int o = 16; o > 0; o >>= 1) s += __shfl_xor_sync(0xffffffffu, s, o);
    if (lane == 0) nrm[row] = s;

    uint4 t;
    asm("cvt.rna.tf32.f32 %0, %1;" : "=r"(t.x) : "f"(v.x));
    asm("cvt.rna.tf32.f32 %0, %1;" : "=r"(t.y) : "f"(v.y));
    asm("cvt.rna.tf32.f32 %0, %1;" : "=r"(t.z) : "f"(v.z));
    asm("cvt.rna.tf32.f32 %0, %1;" : "=r"(t.w) : "f"(v.w));
    reinterpret_cast<uint4*>(dst + (size_t)row * DK)[lane] = t;
}

extern "C" void kernel_launch(void* const* d_in, const int* in_sizes, int n_in,
                              void* d_out, int out_size) {
    const float* A = (const float*)d_in[0];
    const float* B = (const float*)d_in[1];
    float* C = (float*)d_out;

    float *sq1, *sq2, *A32, *B32;
    cudaGetSymbolAddress((void**)&sq1, g_sq1);
    cudaGetSymbolAddress((void**)&sq2, g_sq2);
    cudaGetSymbolAddress((void**)&A32, g_A32);
    cudaGetSymbolAddress((void**)&B32, g_B32);

    cudaFuncSetAttribute(euclid_mma_kernel,
                         cudaFuncAttributeMaxDynamicSharedMemorySize, SM_TOTAL);

    // 2*8192 rows, 8 warps per 256-thread block
    prep_kernel<<<2 * NR / 8, 256>>>(A, B, A32, B32, sq1, sq2);

    dim3 grid(NR / 128 / 4, NR / 128);  // (16, 64): 4 N-tiles per CTA
    euclid_mma_kernel<<<grid, NTHREADS, SM_TOTAL>>>(A32, B32, sq1, sq2, C);
}